// round 15
// baseline (speedup 1.0000x reference)
#include <cuda_runtime.h>
#include <cuda_fp16.h>

// Problem constants (fixed by the dataset; guarded at runtime).
#define NN 100000
#define EE 3200000
#define FF 128
#define F4 (FF / 4)     // 32 float4 per feature row
#define SLOTS 128       // padded slots/node (Poisson(32): P(deg>128) ~ 1e-40)
#define NTILES ((NN + 255) / 256)
#define NWARPS 8        // warps (dest nodes) per block in SpMM

// ---------------- static scratch (no allocations; zero-init at load) ------
__device__ int    g_cnt[NN];                   // in-degree; re-zeroed in spmm step K
__device__ float  g_dinv[NN];
__device__ int    g_rowptr[NN];                // packed-CSR start per node
__device__ int    g_metapad[NN * SLOTS];       // padded scatter target
__device__ int    g_meta[EE];                  // packed src rows (CSR by dest)
__device__ int    g_ticket;                    // lookback ticket (zeroed by scatter)
__device__ unsigned long long g_tile[NTILES];  // (flag<<32)|sum  (zeroed by scatter)
__device__ float4 g_px[NN * F4];               // X' = Dinv*x (fp32 master, P0)
__device__ float4 g_pa[NN * F4];               // fp32 P ping-pong
__device__ float4 g_pb[NN * F4];
__device__ uint2  g_h16a[NN * F4];             // fp16 gather rows (256 B/node)
__device__ uint2  g_h16b[NN * F4];

// ---------------- setup 1: single-pass padded scatter (4 edges/thread) ----
// Also zeroes the lookback state for compact_k (next launch: ordered).
__global__ void scatter_k(const int4* __restrict__ row4, const int4* __restrict__ col4,
                          const int* __restrict__ row, const int* __restrict__ col,
                          int E4, int E) {
    int t = blockIdx.x * blockDim.x + threadIdx.x;

    if (t < NTILES) g_tile[t] = 0ULL;
    if (t == NTILES) g_ticket = 0;

    if (t < E4) {
        int4 c = __ldg(&col4[t]);
        int4 r = __ldg(&row4[t]);
        int p0 = atomicAdd(&g_cnt[c.x], 1);
        int p1 = atomicAdd(&g_cnt[c.y], 1);
        int p2 = atomicAdd(&g_cnt[c.z], 1);
        int p3 = atomicAdd(&g_cnt[c.w], 1);
        if (p0 < SLOTS) g_metapad[(c.x << 7) + p0] = r.x;
        if (p1 < SLOTS) g_metapad[(c.y << 7) + p1] = r.y;
        if (p2 < SLOTS) g_metapad[(c.z << 7) + p2] = r.z;
        if (p3 < SLOTS) g_metapad[(c.w << 7) + p3] = r.w;
    }
    int rem = E4 * 4 + t;                      // tail (E not multiple of 4)
    if (t < (E & 3) && rem < E) {
        int c = col[rem];
        int pos = atomicAdd(&g_cnt[c], 1);
        if (pos < SLOTS) g_metapad[(c << 7) + pos] = row[rem];
    }
}

// ---------------- setup 2 (stream B): dinv + prescale X' ------------------
__global__ void prescale_k(const float4* __restrict__ x4, int n) {
    int gid = blockIdx.x * blockDim.x + threadIdx.x;
    int stride = gridDim.x * blockDim.x;

    for (int i = gid; i < n; i += stride) {
        int d = g_cnt[i];
        g_dinv[i] = (d > 0) ? rsqrtf((float)d) : 0.0f;
    }

    int total = n * F4;
    for (int j = gid; j < total; j += stride) {
        int d = g_cnt[j >> 5];
        float s = (d > 0) ? rsqrtf((float)d) : 0.0f;  // recompute: no x-block dep
        float4 v = x4[j];
        v.x *= s; v.y *= s; v.z *= s; v.w *= s;
        g_px[j] = v;
        __half2 h01 = __floats2half2_rn(v.x, v.y);
        __half2 h23 = __floats2half2_rn(v.z, v.w);
        uint2 u;
        u.x = *(unsigned int*)&h01;
        u.y = *(unsigned int*)&h23;
        g_h16a[j] = u;
    }
}

// ---------------- setup 3 (stream A): decoupled-lookback scan + compact ---
// One block = 256 nodes: scan cnt -> packed start offsets, write rowptr,
// copy each node's slots padded -> packed.
__global__ void __launch_bounds__(256)
compact_k(int n) {
    __shared__ int sbid;
    __shared__ int wsum[8];
    __shared__ int sprefix;
    __shared__ int sstart[256];
    __shared__ int scnt[256];

    const unsigned FULL = 0xffffffffu;
    int tid = threadIdx.x, lane = tid & 31, w = tid >> 5;

    if (tid == 0) sbid = atomicAdd(&g_ticket, 1);
    __syncthreads();
    int bid = sbid;

    int i = bid * 256 + tid;
    int c = 0;
    if (i < n) {
        c = g_cnt[i];
        if (c > SLOTS) c = SLOTS;
    }

    // Block-level inclusive scan of c.
    int s = c;
    #pragma unroll
    for (int o = 1; o < 32; o <<= 1) {
        int t2 = __shfl_up_sync(FULL, s, o);
        if (lane >= o) s += t2;
    }
    if (lane == 31) wsum[w] = s;
    __syncthreads();
    if (w == 0) {
        int ws = (lane < 8) ? wsum[lane] : 0;
        #pragma unroll
        for (int o = 1; o < 8; o <<= 1) {
            int t2 = __shfl_up_sync(FULL, ws, o);
            if (lane >= o) ws += t2;
        }
        if (lane < 8) wsum[lane] = ws;
    }
    __syncthreads();
    int excl = s - c + ((w > 0) ? wsum[w - 1] : 0);  // block-exclusive
    int agg  = wsum[7];                               // block total

    // Decoupled lookback (flag|value in one 64-bit word: 1=agg, 2=inclusive).
    if (tid == 0) {
        int exclusive = 0;
        if (bid == 0) {
            atomicExch(&g_tile[0], (2ULL << 32) | (unsigned long long)(unsigned)agg);
        } else {
            atomicExch(&g_tile[bid], (1ULL << 32) | (unsigned long long)(unsigned)agg);
            int j = bid - 1;
            int run = 0;
            while (true) {
                unsigned long long v = atomicAdd(&g_tile[j], 0ULL);
                unsigned flag = (unsigned)(v >> 32);
                if (flag == 0u) { __nanosleep(32); continue; }
                run += (int)(unsigned)v;
                if (flag == 2u) break;
                j--;
            }
            exclusive = run;
            atomicExch(&g_tile[bid],
                       (2ULL << 32) | (unsigned long long)(unsigned)(run + agg));
        }
        sprefix = exclusive;
    }
    __syncthreads();

    int start = sprefix + excl;
    if (i < n) g_rowptr[i] = start;
    sstart[tid] = start;
    scnt[tid]   = c;                                  // 0 for i >= n
    __syncthreads();

    // Copy padded -> packed. Warp w handles nodes [w*32, w*32+32).
    int nb = bid * 256;
    for (int nd = w * 32; nd < w * 32 + 32; nd++) {
        int cc = scnt[nd];
        int st = sstart[nd];
        int node = nb + nd;
        for (int e = lane; e < cc; e += 32)
            g_meta[st + e] = g_metapad[(node << 7) + e];
    }
}

// ---------------- fused SpMM (fp16 uint2 gather, 1 edge/iter) -------------
// Scaled space: P'_i = Dinv * P_i; gather is unweighted sum over in-edges.
//   step 1:  P'_1 = d2*S;              acc = mf0*X' + w1*P'_1
//   step>=2: P'_i = 2*d2*S - P'_{i-2}; acc += wi*P'_i
//   step K:  out = acc * sqrt(deg); isolated analytic; re-zeroes g_cnt.
__global__ void __launch_bounds__(NWARPS * 32)
spmm_k(const uint2*  __restrict__ h16,     // fp16 P'_{i-1} (gather source)
       const float4* __restrict__ pprev2,  // fp32 P'_{i-2} (X' at step 1/2)
       float4*       pout,                 // fp32 P'_i (may alias pprev2; per-thread RMW)
       uint2*        __restrict__ pout16,  // fp16 P'_i
       float4*       __restrict__ acc,
       const float4* __restrict__ x4,
       const float*  __restrict__ mf,
       const float*  __restrict__ lap,
       int step, int K, int n) {
    __shared__ int smeta[NWARPS][32];
    int wid = threadIdx.x >> 5;
    int lane = threadIdx.x & 31;
    int c = blockIdx.x * NWARPS + wid;
    if (c >= n) return;

    int start = g_rowptr[c];
    int cnt   = g_cnt[c];
    if (cnt > SLOTS) cnt = SLOTS;
    int end = start + cnt;

    float sx = 0.f, sy = 0.f, sz = 0.f, sw = 0.f;

    for (int base = start; base < end; base += 32) {
        int m = end - base;
        if (m > 32) m = 32;
        if (lane < m) smeta[wid][lane] = g_meta[base + lane];
        __syncwarp();
        #pragma unroll 8
        for (int k = 0; k < m; k++) {
            int r = smeta[wid][k];
            uint2 hv = __ldg(&h16[r * F4 + lane]);
            float2 fa = __half22float2(*(const __half2*)&hv.x);
            float2 fb = __half22float2(*(const __half2*)&hv.y);
            sx += fa.x; sy += fa.y; sz += fb.x; sw += fb.y;
        }
        __syncwarp();
    }

    int idx = c * F4 + lane;
    float dinv = g_dinv[c];
    float d2 = dinv * dinv;
    float wi = lap[step - 1] * mf[step];

    float4 p, a;
    if (step == 1) {
        float w0 = mf[0];
        float4 xp = pprev2[idx];              // X'
        p.x = d2 * sx; p.y = d2 * sy; p.z = d2 * sz; p.w = d2 * sw;
        a.x = w0 * xp.x + wi * p.x;
        a.y = w0 * xp.y + wi * p.y;
        a.z = w0 * xp.z + wi * p.z;
        a.w = w0 * xp.w + wi * p.w;
    } else {
        float4 p2 = pprev2[idx];
        float td2 = 2.f * d2;
        p.x = td2 * sx - p2.x;
        p.y = td2 * sy - p2.y;
        p.z = td2 * sz - p2.z;
        p.w = td2 * sw - p2.w;
        a = acc[idx];
        a.x += wi * p.x;
        a.y += wi * p.y;
        a.z += wi * p.z;
        a.w += wi * p.w;
    }

    if (step < K) {
        acc[idx] = a;
        if (step + 2 <= K) pout[idx] = p;     // fp32 master only if a later step reads it
        __half2 h01 = __floats2half2_rn(p.x, p.y);
        __half2 h23 = __floats2half2_rn(p.z, p.w);
        uint2 u;
        u.x = *(unsigned int*)&h01;
        u.y = *(unsigned int*)&h23;
        pout16[idx] = u;
    } else {
        if (dinv > 0.f) {
            float sd = 1.0f / dinv;           // = sqrt(deg) (+~1ulp, negligible)
            a.x *= sd; a.y *= sd; a.z *= sd; a.w *= sd;
            acc[idx] = a;
        } else {
            // isolated node: P_{2j} = (-1)^j x, P_odd = 0
            float cE = mf[0];
            float sgn = -1.f;
            for (int j = 2; j <= K; j += 2) {
                cE += sgn * lap[j - 1] * mf[j];
                sgn = -sgn;
            }
            float4 xv = x4[idx];
            xv.x *= cE; xv.y *= cE; xv.z *= cE; xv.w *= cE;
            acc[idx] = xv;
        }
        if (lane == 0) g_cnt[c] = 0;          // ready for the next harness call
    }
}

// ---------------- launch ----------------
extern "C" void kernel_launch(void* const* d_in, const int* in_sizes, int n_in,
                              void* d_out, int out_size) {
    const float* x   = (const float*)d_in[0];
    const float* mf  = (const float*)d_in[1];   // (1, K+1, 1)
    const float* lap = (const float*)d_in[2];   // (K+1,)
    const int*   ei  = (const int*)d_in[3];     // (2, E) row-major

    int E = in_sizes[3] / 2;
    int K = in_sizes[2] - 1;
    int n = in_sizes[0] / FF;
    if (n > NN) n = NN;
    if (E > EE) E = EE;
    if (K < 1) K = 1;

    const int* rowp = ei;
    const int* colp = ei + E;
    float4* out = (float4*)d_out;
    const float4* x4 = (const float4*)x;

    int tb = 256;
    int E4 = E >> 2;

    // One side stream + events, created once (host-side objects only).
    static cudaStream_t sB = nullptr;
    static cudaEvent_t evFork = nullptr, evJoin = nullptr;
    if (sB == nullptr) {
        cudaStreamCreateWithFlags(&sB, cudaStreamNonBlocking);
        cudaEventCreateWithFlags(&evFork, cudaEventDisableTiming);
        cudaEventCreateWithFlags(&evJoin, cudaEventDisableTiming);
    }

    // Stream A: padded scatter (also zeroes lookback state).
    int sg = (E4 + tb - 1) / tb;
    if (sg < (NTILES + 1 + tb - 1) / tb + 1) sg = (NTILES + 1 + tb - 1) / tb + 1;
    scatter_k<<<sg, tb>>>((const int4*)rowp, (const int4*)colp, rowp, colp, E4, E);

    // Fork: prescale on stream B (needs only g_cnt); compact on stream A.
    cudaEventRecord(evFork, 0);
    cudaStreamWaitEvent(sB, evFork, 0);
    prescale_k<<<(n * F4 + tb - 1) / tb, tb, 0, sB>>>(x4, n);
    cudaEventRecord(evJoin, sB);

    compact_k<<<(n + 255) / 256, 256>>>(n);
    cudaStreamWaitEvent(0, evJoin, 0);        // join before step 1

    void *px, *pa, *pb, *ha, *hb;
    cudaGetSymbolAddress(&px, g_px);
    cudaGetSymbolAddress(&pa, g_pa);
    cudaGetSymbolAddress(&pb, g_pb);
    cudaGetSymbolAddress(&ha, g_h16a);
    cudaGetSymbolAddress(&hb, g_h16b);

    float4* f32buf[2] = {(float4*)pb, (float4*)pa};   // step i -> f32buf[i&1]
    uint2*  h16buf[2] = {(uint2*)ha, (uint2*)hb};     // P_i (fp16) -> h16buf[i&1]

    int grid = (n + NWARPS - 1) / NWARPS;

    for (int step = 1; step <= K; step++) {
        const uint2* h16 = h16buf[(step - 1) & 1];     // P_{i-1}
        uint2* p16out    = h16buf[step & 1];
        float4* pout     = f32buf[step & 1];
        const float4* pprev2 =
            (step <= 2) ? (const float4*)px                 // X' (P0) for steps 1,2
                        : (const float4*)f32buf[step & 1];  // same-parity buffer (RMW)
        spmm_k<<<grid, NWARPS * 32>>>(h16, pprev2, pout, p16out, out, x4,
                                      mf, lap, step, K, n);
    }
}

// round 16
// speedup vs baseline: 1.1451x; 1.1451x over previous
#include <cuda_runtime.h>
#include <cuda_fp16.h>

// Problem constants (fixed by the dataset; guarded at runtime).
#define NN 100000
#define EE 3200000
#define FF 128
#define F4 (FF / 4)   // 32 float4 per feature row
#define NWARPS 8      // warps (dest nodes) per block in SpMM
#define NT1024 ((NN + 1023) / 1024)   // lookback tiles (1024 nodes/tile)

// ---------------- static scratch (no allocations; zero-init at load) ------
__device__ int    g_deg[NN];                  // re-zeroed in spmm step K
__device__ float  g_dinv[NN];
__device__ float  g_sqd[NN];
__device__ int    g_rowptr[NN + 1];
__device__ int    g_curptr[NN];
__device__ int    g_meta[EE];                 // src row index, packed CSR by dest
__device__ int    g_ticket;                   // lookback ticket (zeroed by hist)
__device__ unsigned long long g_tile[NT1024]; // (flag<<32)|sum (zeroed by hist)
__device__ float4 g_px[NN * F4];              // X' = Dinv*x (fp32 master, P0)
__device__ float4 g_pa[NN * F4];              // fp32 P ping-pong
__device__ float4 g_pb[NN * F4];
__device__ uint2  g_h16a[NN * F4];            // fp16 gather rows (256 B/node)
__device__ uint2  g_h16b[NN * F4];

// ---------------- setup 1: in-degree histogram (4 edges/thread) -----------
// Also zeroes the lookback state for scanlb_k (strictly-prior launch).
__global__ void hist_k(const int4* __restrict__ col4, int E4,
                       const int* __restrict__ col, int E) {
    int t = blockIdx.x * blockDim.x + threadIdx.x;

    if (t < NT1024) g_tile[t] = 0ULL;
    if (t == NT1024) g_ticket = 0;

    if (t < E4) {
        int4 c = __ldg(&col4[t]);
        atomicAdd(&g_deg[c.x], 1);
        atomicAdd(&g_deg[c.y], 1);
        atomicAdd(&g_deg[c.z], 1);
        atomicAdd(&g_deg[c.w], 1);
    }
    int rem = E4 * 4 + t;                     // tail (E not multiple of 4)
    if (t < (E & 3) && rem < E) atomicAdd(&g_deg[col[rem]], 1);
}

// ---------------- setup 2: decoupled-lookback scan -> rowptr/curptr -------
// Single kernel: block scan of deg (1024/tile) + cross-tile lookback.
// Also emits dinv/sqd.
__global__ void __launch_bounds__(1024)
scanlb_k(int n, int E) {
    __shared__ int sbid;
    __shared__ int wsum[32];
    __shared__ int sprefix;

    const unsigned FULL = 0xffffffffu;
    int tid = threadIdx.x, lane = tid & 31, w = tid >> 5;

    if (tid == 0) sbid = atomicAdd(&g_ticket, 1);
    __syncthreads();
    int bid = sbid;

    int i = bid * 1024 + tid;
    int v = (i < n) ? g_deg[i] : 0;
    if (i < n) {
        g_dinv[i] = (v > 0) ? rsqrtf((float)v) : 0.0f;
        g_sqd[i]  = (v > 0) ? sqrtf((float)v)  : 0.0f;
    }

    // Block-level inclusive scan.
    int s = v;
    #pragma unroll
    for (int o = 1; o < 32; o <<= 1) {
        int t2 = __shfl_up_sync(FULL, s, o);
        if (lane >= o) s += t2;
    }
    if (lane == 31) wsum[w] = s;
    __syncthreads();
    if (w == 0) {
        int ws = wsum[lane];
        #pragma unroll
        for (int o = 1; o < 32; o <<= 1) {
            int t2 = __shfl_up_sync(FULL, ws, o);
            if (lane >= o) ws += t2;
        }
        wsum[lane] = ws;
    }
    __syncthreads();
    int incl = s + ((w > 0) ? wsum[w - 1] : 0);   // block-inclusive
    int agg  = wsum[31];                           // block total

    // Decoupled lookback (flag|value packed: 1=aggregate, 2=inclusive).
    if (tid == 0) {
        int exclusive = 0;
        if (bid == 0) {
            atomicExch(&g_tile[0], (2ULL << 32) | (unsigned long long)(unsigned)agg);
        } else {
            atomicExch(&g_tile[bid], (1ULL << 32) | (unsigned long long)(unsigned)agg);
            int j = bid - 1;
            int run = 0;
            while (true) {
                unsigned long long t3 = atomicAdd(&g_tile[j], 0ULL);
                unsigned flag = (unsigned)(t3 >> 32);
                if (flag == 0u) { __nanosleep(32); continue; }
                run += (int)(unsigned)t3;
                if (flag == 2u) break;
                j--;
            }
            exclusive = run;
            atomicExch(&g_tile[bid],
                       (2ULL << 32) | (unsigned long long)(unsigned)(run + agg));
        }
        sprefix = exclusive;
    }
    __syncthreads();

    if (i < n) {
        int excl = sprefix + incl - v;             // global exclusive
        g_rowptr[i] = excl;
        g_curptr[i] = excl;
    }
    if (bid == 0 && tid == 0) g_rowptr[n] = E;
}

// ---------------- setup 3 (stream B, overlapped): prescale X' -------------
__global__ void prescale_k(const float4* __restrict__ x4, int n) {
    int gid = blockIdx.x * blockDim.x + threadIdx.x;
    int stride = gridDim.x * blockDim.x;
    int total = n * F4;
    for (int j = gid; j < total; j += stride) {
        float s = g_dinv[j >> 5];
        float4 v = x4[j];
        v.x *= s; v.y *= s; v.z *= s; v.w *= s;
        g_px[j] = v;
        __half2 h01 = __floats2half2_rn(v.x, v.y);
        __half2 h23 = __floats2half2_rn(v.z, v.w);
        uint2 u;
        u.x = *(unsigned int*)&h01;
        u.y = *(unsigned int*)&h23;
        g_h16a[j] = u;
    }
}

// ---------------- setup 4 (stream A): scatter (4 edges/thread) ------------
__global__ void scatter_k(const int4* __restrict__ row4, const int4* __restrict__ col4,
                          const int* __restrict__ row, const int* __restrict__ col,
                          int E4, int E) {
    int t = blockIdx.x * blockDim.x + threadIdx.x;
    if (t < E4) {
        int4 c = __ldg(&col4[t]);
        int4 r = __ldg(&row4[t]);
        int p0 = atomicAdd(&g_curptr[c.x], 1);
        int p1 = atomicAdd(&g_curptr[c.y], 1);
        int p2 = atomicAdd(&g_curptr[c.z], 1);
        int p3 = atomicAdd(&g_curptr[c.w], 1);
        g_meta[p0] = r.x;
        g_meta[p1] = r.y;
        g_meta[p2] = r.z;
        g_meta[p3] = r.w;
    }
    int rem = E4 * 4 + t;
    if (t < (E & 3) && rem < E) {
        int pos = atomicAdd(&g_curptr[col[rem]], 1);
        g_meta[pos] = row[rem];
    }
}

// ---------------- fused SpMM (fp16 uint2 gather, 1 edge/iter) -------------
// Scaled space: P'_i = Dinv * P_i; gather is unweighted sum over in-edges.
//   step 1:  P'_1 = d2*S;              acc = mf0*X' + w1*P'_1
//   step>=2: P'_i = 2*d2*S - P'_{i-2}; acc += wi*P'_i
//   step K:  out = acc * sqrt(deg); isolated nodes analytic; re-zeroes g_deg.
__global__ void __launch_bounds__(NWARPS * 32)
spmm_k(const uint2*  __restrict__ h16,     // fp16 P'_{i-1} (gather source)
       const float4* __restrict__ pprev2,  // fp32 P'_{i-2} (X' at step 1/2)
       float4*       pout,                 // fp32 P'_i (may alias pprev2; per-thread RMW)
       uint2*        __restrict__ pout16,  // fp16 P'_i
       float4*       __restrict__ acc,
       const float4* __restrict__ x4,
       const float*  __restrict__ mf,
       const float*  __restrict__ lap,
       int step, int K, int n) {
    __shared__ int smeta[NWARPS][32];
    int wid = threadIdx.x >> 5;
    int lane = threadIdx.x & 31;
    int c = blockIdx.x * NWARPS + wid;
    if (c >= n) return;

    int start = g_rowptr[c];
    int end   = g_rowptr[c + 1];

    float sx = 0.f, sy = 0.f, sz = 0.f, sw = 0.f;

    for (int base = start; base < end; base += 32) {
        int m = end - base;
        if (m > 32) m = 32;
        if (lane < m) smeta[wid][lane] = g_meta[base + lane];
        __syncwarp();
        #pragma unroll 8
        for (int k = 0; k < m; k++) {
            int r = smeta[wid][k];
            uint2 hv = __ldg(&h16[r * F4 + lane]);
            float2 fa = __half22float2(*(const __half2*)&hv.x);
            float2 fb = __half22float2(*(const __half2*)&hv.y);
            sx += fa.x; sy += fa.y; sz += fb.x; sw += fb.y;
        }
        __syncwarp();
    }

    int idx = c * F4 + lane;
    float dinv = g_dinv[c];
    float d2 = dinv * dinv;
    float wi = lap[step - 1] * mf[step];

    float4 p, a;
    if (step == 1) {
        float w0 = mf[0];
        float4 xp = pprev2[idx];              // X'
        p.x = d2 * sx; p.y = d2 * sy; p.z = d2 * sz; p.w = d2 * sw;
        a.x = w0 * xp.x + wi * p.x;
        a.y = w0 * xp.y + wi * p.y;
        a.z = w0 * xp.z + wi * p.z;
        a.w = w0 * xp.w + wi * p.w;
    } else {
        float4 p2 = pprev2[idx];
        float td2 = 2.f * d2;
        p.x = td2 * sx - p2.x;
        p.y = td2 * sy - p2.y;
        p.z = td2 * sz - p2.z;
        p.w = td2 * sw - p2.w;
        a = acc[idx];
        a.x += wi * p.x;
        a.y += wi * p.y;
        a.z += wi * p.z;
        a.w += wi * p.w;
    }

    if (step < K) {
        acc[idx] = a;
        if (step + 2 <= K) pout[idx] = p;     // fp32 master only if a later step reads it
        __half2 h01 = __floats2half2_rn(p.x, p.y);
        __half2 h23 = __floats2half2_rn(p.z, p.w);
        uint2 u;
        u.x = *(unsigned int*)&h01;
        u.y = *(unsigned int*)&h23;
        pout16[idx] = u;
    } else {
        float sd = g_sqd[c];
        if (sd > 0.f) {
            a.x *= sd; a.y *= sd; a.z *= sd; a.w *= sd;
            acc[idx] = a;
        } else {
            // isolated node: P_{2j} = (-1)^j x, P_odd = 0
            float cE = mf[0];
            float sgn = -1.f;
            for (int j = 2; j <= K; j += 2) {
                cE += sgn * lap[j - 1] * mf[j];
                sgn = -sgn;
            }
            float4 xv = x4[idx];
            xv.x *= cE; xv.y *= cE; xv.z *= cE; xv.w *= cE;
            acc[idx] = xv;
        }
        if (lane == 0) g_deg[c] = 0;          // ready for the next harness call
    }
}

// ---------------- launch ----------------
extern "C" void kernel_launch(void* const* d_in, const int* in_sizes, int n_in,
                              void* d_out, int out_size) {
    const float* x   = (const float*)d_in[0];
    const float* mf  = (const float*)d_in[1];   // (1, K+1, 1)
    const float* lap = (const float*)d_in[2];   // (K+1,)
    const int*   ei  = (const int*)d_in[3];     // (2, E) row-major

    int E = in_sizes[3] / 2;
    int K = in_sizes[2] - 1;
    int n = in_sizes[0] / FF;
    if (n > NN) n = NN;
    if (E > EE) E = EE;
    if (K < 1) K = 1;

    const int* rowp = ei;
    const int* colp = ei + E;
    float4* out = (float4*)d_out;
    const float4* x4 = (const float4*)x;

    int tb = 256;
    int nb = (n + 1023) / 1024;
    int E4 = E >> 2;

    // One side stream + events, created once (host-side objects only).
    static cudaStream_t sB = nullptr;
    static cudaEvent_t evFork = nullptr, evJoin = nullptr;
    if (sB == nullptr) {
        cudaStreamCreateWithFlags(&sB, cudaStreamNonBlocking);
        cudaEventCreateWithFlags(&evFork, cudaEventDisableTiming);
        cudaEventCreateWithFlags(&evJoin, cudaEventDisableTiming);
    }

    // Stream A: hist (also zeroes lookback state) -> lookback scan.
    hist_k<<<(E4 + tb - 1) / tb, tb>>>((const int4*)colp, E4, colp, E);
    scanlb_k<<<nb, 1024>>>(n, E);

    // Fork: prescale (needs only dinv from scanlb) overlaps scatter.
    cudaEventRecord(evFork, 0);
    cudaStreamWaitEvent(sB, evFork, 0);
    prescale_k<<<(n * F4 + tb - 1) / tb, tb, 0, sB>>>(x4, n);
    cudaEventRecord(evJoin, sB);

    scatter_k<<<(E4 + tb - 1) / tb, tb>>>((const int4*)rowp, (const int4*)colp,
                                          rowp, colp, E4, E);
    cudaStreamWaitEvent(0, evJoin, 0);        // join before step 1

    void *px, *pa, *pb, *ha, *hb;
    cudaGetSymbolAddress(&px, g_px);
    cudaGetSymbolAddress(&pa, g_pa);
    cudaGetSymbolAddress(&pb, g_pb);
    cudaGetSymbolAddress(&ha, g_h16a);
    cudaGetSymbolAddress(&hb, g_h16b);

    float4* f32buf[2] = {(float4*)pb, (float4*)pa};   // step i -> f32buf[i&1]
    uint2*  h16buf[2] = {(uint2*)ha, (uint2*)hb};     // P_i (fp16) -> h16buf[i&1]

    int grid = (n + NWARPS - 1) / NWARPS;

    for (int step = 1; step <= K; step++) {
        const uint2* h16 = h16buf[(step - 1) & 1];     // P_{i-1}
        uint2* p16out    = h16buf[step & 1];
        float4* pout     = f32buf[step & 1];
        const float4* pprev2 =
            (step <= 2) ? (const float4*)px                 // X' (P0) for steps 1,2
                        : (const float4*)f32buf[step & 1];  // same-parity buffer (RMW)
        spmm_k<<<grid, NWARPS * 32>>>(h16, pprev2, pout, p16out, out, x4,
                                      mf, lap, step, K, n);
    }
}

// round 17
// speedup vs baseline: 1.1595x; 1.0126x over previous
#include <cuda_runtime.h>
#include <cuda_fp16.h>

// Problem constants (fixed by the dataset; guarded at runtime).
#define NN 100000
#define EE 3200000
#define FF 128
#define F4 (FF / 4)   // 32 float4 per feature row
#define NWARPS 8      // warps (dest nodes) per block in SpMM
#define NT1024 ((NN + 1023) / 1024)   // lookback tiles (1024 nodes/tile)

// ---------------- static scratch (no allocations; zero-init at load) ------
__device__ int    g_deg[NN];                  // re-zeroed in spmm step K
__device__ float  g_dinv[NN];
__device__ float  g_sqd[NN];
__device__ int    g_rowptr[NN + 1];
__device__ int    g_curptr[NN];
__device__ int    g_meta[EE];                 // src row index, packed CSR by dest
__device__ int    g_ticket;                   // lookback ticket (zeroed by hist)
__device__ unsigned long long g_tile[NT1024]; // (flag<<32)|sum (zeroed by hist)
__device__ float4 g_px[NN * F4];              // X' = Dinv*x (fp32 master, P0)
__device__ float4 g_pa[NN * F4];              // fp32 P ping-pong
__device__ float4 g_pb[NN * F4];
__device__ uint2  g_h16a[NN * F4];            // fp16 gather rows (256 B/node)
__device__ uint2  g_h16b[NN * F4];

// ---------------- setup 1: in-degree histogram (4 edges/thread) -----------
// Also zeroes the lookback state for scanlb_k (strictly-prior launch).
__global__ void hist_k(const int4* __restrict__ col4, int E4,
                       const int* __restrict__ col, int E) {
    int t = blockIdx.x * blockDim.x + threadIdx.x;

    if (t < NT1024) g_tile[t] = 0ULL;
    if (t == NT1024) g_ticket = 0;

    if (t < E4) {
        int4 c = __ldg(&col4[t]);
        atomicAdd(&g_deg[c.x], 1);
        atomicAdd(&g_deg[c.y], 1);
        atomicAdd(&g_deg[c.z], 1);
        atomicAdd(&g_deg[c.w], 1);
    }
    int rem = E4 * 4 + t;                     // tail (E not multiple of 4)
    if (t < (E & 3) && rem < E) atomicAdd(&g_deg[col[rem]], 1);
}

// ---------------- setup 2: decoupled-lookback scan -> rowptr/curptr -------
__global__ void __launch_bounds__(1024)
scanlb_k(int n, int E) {
    __shared__ int sbid;
    __shared__ int wsum[32];
    __shared__ int sprefix;

    const unsigned FULL = 0xffffffffu;
    int tid = threadIdx.x, lane = tid & 31, w = tid >> 5;

    if (tid == 0) sbid = atomicAdd(&g_ticket, 1);
    __syncthreads();
    int bid = sbid;

    int i = bid * 1024 + tid;
    int v = (i < n) ? g_deg[i] : 0;
    if (i < n) {
        g_dinv[i] = (v > 0) ? rsqrtf((float)v) : 0.0f;
        g_sqd[i]  = (v > 0) ? sqrtf((float)v)  : 0.0f;
    }

    int s = v;
    #pragma unroll
    for (int o = 1; o < 32; o <<= 1) {
        int t2 = __shfl_up_sync(FULL, s, o);
        if (lane >= o) s += t2;
    }
    if (lane == 31) wsum[w] = s;
    __syncthreads();
    if (w == 0) {
        int ws = wsum[lane];
        #pragma unroll
        for (int o = 1; o < 32; o <<= 1) {
            int t2 = __shfl_up_sync(FULL, ws, o);
            if (lane >= o) ws += t2;
        }
        wsum[lane] = ws;
    }
    __syncthreads();
    int incl = s + ((w > 0) ? wsum[w - 1] : 0);   // block-inclusive
    int agg  = wsum[31];                           // block total

    if (tid == 0) {
        int exclusive = 0;
        if (bid == 0) {
            atomicExch(&g_tile[0], (2ULL << 32) | (unsigned long long)(unsigned)agg);
        } else {
            atomicExch(&g_tile[bid], (1ULL << 32) | (unsigned long long)(unsigned)agg);
            int j = bid - 1;
            int run = 0;
            while (true) {
                unsigned long long t3 = atomicAdd(&g_tile[j], 0ULL);
                unsigned flag = (unsigned)(t3 >> 32);
                if (flag == 0u) { __nanosleep(32); continue; }
                run += (int)(unsigned)t3;
                if (flag == 2u) break;
                j--;
            }
            exclusive = run;
            atomicExch(&g_tile[bid],
                       (2ULL << 32) | (unsigned long long)(unsigned)(run + agg));
        }
        sprefix = exclusive;
    }
    __syncthreads();

    if (i < n) {
        int excl = sprefix + incl - v;             // global exclusive
        g_rowptr[i] = excl;
        g_curptr[i] = excl;
    }
    if (bid == 0 && tid == 0) g_rowptr[n] = E;
}

// ---------------- setup 3 (stream B, overlapped): prescale X' -------------
__global__ void prescale_k(const float4* __restrict__ x4, int n) {
    int gid = blockIdx.x * blockDim.x + threadIdx.x;
    int stride = gridDim.x * blockDim.x;
    int total = n * F4;
    for (int j = gid; j < total; j += stride) {
        float s = g_dinv[j >> 5];
        float4 v = x4[j];
        v.x *= s; v.y *= s; v.z *= s; v.w *= s;
        g_px[j] = v;
        __half2 h01 = __floats2half2_rn(v.x, v.y);
        __half2 h23 = __floats2half2_rn(v.z, v.w);
        uint2 u;
        u.x = *(unsigned int*)&h01;
        u.y = *(unsigned int*)&h23;
        g_h16a[j] = u;
    }
}

// ---------------- setup 4 (stream A): scatter (4 edges/thread) ------------
__global__ void scatter_k(const int4* __restrict__ row4, const int4* __restrict__ col4,
                          const int* __restrict__ row, const int* __restrict__ col,
                          int E4, int E) {
    int t = blockIdx.x * blockDim.x + threadIdx.x;
    if (t < E4) {
        int4 c = __ldg(&col4[t]);
        int4 r = __ldg(&row4[t]);
        int p0 = atomicAdd(&g_curptr[c.x], 1);
        int p1 = atomicAdd(&g_curptr[c.y], 1);
        int p2 = atomicAdd(&g_curptr[c.z], 1);
        int p3 = atomicAdd(&g_curptr[c.w], 1);
        g_meta[p0] = r.x;
        g_meta[p1] = r.y;
        g_meta[p2] = r.z;
        g_meta[p3] = r.w;
    }
    int rem = E4 * 4 + t;
    if (t < (E & 3) && rem < E) {
        int pos = atomicAdd(&g_curptr[col[rem]], 1);
        g_meta[pos] = row[rem];
    }
}

// ---------------- fused SpMM (fp16 uint2 gather, 1 edge/iter) -------------
// Scaled space: P'_i = Dinv * P_i; gather is unweighted sum over in-edges.
//   step 1:  P'_1 = d2*S;              acc = mf0*X' + w1*P'_1
//   step>=2: P'_i = 2*d2*S - P'_{i-2}; acc += wi*P'_i
//   step K:  out = acc * sqrt(deg); isolated nodes analytic; re-zeroes g_deg.
// L2 shaping: streaming operands (pprev2/acc/fp32 pout) use .cs so the hot
// gather source (h16) + meta keep L2 residency; DRAM has 70% headroom.
__global__ void __launch_bounds__(NWARPS * 32)
spmm_k(const uint2*  __restrict__ h16,     // fp16 P'_{i-1} (gather source)
       const float4* __restrict__ pprev2,  // fp32 P'_{i-2} (X' at step 1/2)
       float4*       pout,                 // fp32 P'_i (may alias pprev2; per-thread RMW)
       uint2*        __restrict__ pout16,  // fp16 P'_i
       float4*       __restrict__ acc,
       const float4* __restrict__ x4,
       const float*  __restrict__ mf,
       const float*  __restrict__ lap,
       int step, int K, int n) {
    __shared__ int smeta[NWARPS][32];
    int wid = threadIdx.x >> 5;
    int lane = threadIdx.x & 31;
    int c = blockIdx.x * NWARPS + wid;
    if (c >= n) return;

    int start = g_rowptr[c];
    int end   = g_rowptr[c + 1];

    float sx = 0.f, sy = 0.f, sz = 0.f, sw = 0.f;

    for (int base = start; base < end; base += 32) {
        int m = end - base;
        if (m > 32) m = 32;
        if (lane < m) smeta[wid][lane] = g_meta[base + lane];
        __syncwarp();
        #pragma unroll 8
        for (int k = 0; k < m; k++) {
            int r = smeta[wid][k];
            uint2 hv = __ldg(&h16[r * F4 + lane]);
            float2 fa = __half22float2(*(const __half2*)&hv.x);
            float2 fb = __half22float2(*(const __half2*)&hv.y);
            sx += fa.x; sy += fa.y; sz += fb.x; sw += fb.y;
        }
        __syncwarp();
    }

    int idx = c * F4 + lane;
    float dinv = g_dinv[c];
    float d2 = dinv * dinv;
    float wi = lap[step - 1] * mf[step];

    float4 p, a;
    if (step == 1) {
        float w0 = mf[0];
        float4 xp = __ldcs(&pprev2[idx]);     // X' (streaming)
        p.x = d2 * sx; p.y = d2 * sy; p.z = d2 * sz; p.w = d2 * sw;
        a.x = w0 * xp.x + wi * p.x;
        a.y = w0 * xp.y + wi * p.y;
        a.z = w0 * xp.z + wi * p.z;
        a.w = w0 * xp.w + wi * p.w;
    } else {
        float4 p2 = __ldcs(&pprev2[idx]);     // streaming: read once per step
        float td2 = 2.f * d2;
        p.x = td2 * sx - p2.x;
        p.y = td2 * sy - p2.y;
        p.z = td2 * sz - p2.z;
        p.w = td2 * sw - p2.w;
        a = __ldcs(&acc[idx]);
        a.x += wi * p.x;
        a.y += wi * p.y;
        a.z += wi * p.z;
        a.w += wi * p.w;
    }

    if (step < K) {
        __stcs(&acc[idx], a);
        if (step + 2 <= K) __stcs(&pout[idx], p);  // reread 2 steps later (DRAM ok)
        __half2 h01 = __floats2half2_rn(p.x, p.y);
        __half2 h23 = __floats2half2_rn(p.z, p.w);
        uint2 u;
        u.x = *(unsigned int*)&h01;
        u.y = *(unsigned int*)&h23;
        pout16[idx] = u;                      // next gather source: keep in L2
    } else {
        float sd = g_sqd[c];
        if (sd > 0.f) {
            a.x *= sd; a.y *= sd; a.z *= sd; a.w *= sd;
            acc[idx] = a;
        } else {
            // isolated node: P_{2j} = (-1)^j x, P_odd = 0
            float cE = mf[0];
            float sgn = -1.f;
            for (int j = 2; j <= K; j += 2) {
                cE += sgn * lap[j - 1] * mf[j];
                sgn = -sgn;
            }
            float4 xv = x4[idx];
            xv.x *= cE; xv.y *= cE; xv.z *= cE; xv.w *= cE;
            acc[idx] = xv;
        }
        if (lane == 0) g_deg[c] = 0;          // ready for the next harness call
    }
}

// ---------------- launch ----------------
extern "C" void kernel_launch(void* const* d_in, const int* in_sizes, int n_in,
                              void* d_out, int out_size) {
    const float* x   = (const float*)d_in[0];
    const float* mf  = (const float*)d_in[1];   // (1, K+1, 1)
    const float* lap = (const float*)d_in[2];   // (K+1,)
    const int*   ei  = (const int*)d_in[3];     // (2, E) row-major

    int E = in_sizes[3] / 2;
    int K = in_sizes[2] - 1;
    int n = in_sizes[0] / FF;
    if (n > NN) n = NN;
    if (E > EE) E = EE;
    if (K < 1) K = 1;

    const int* rowp = ei;
    const int* colp = ei + E;
    float4* out = (float4*)d_out;
    const float4* x4 = (const float4*)x;

    int tb = 256;
    int nb = (n + 1023) / 1024;
    int E4 = E >> 2;

    // One side stream + events, created once (host-side objects only).
    static cudaStream_t sB = nullptr;
    static cudaEvent_t evFork = nullptr, evJoin = nullptr;
    if (sB == nullptr) {
        cudaStreamCreateWithFlags(&sB, cudaStreamNonBlocking);
        cudaEventCreateWithFlags(&evFork, cudaEventDisableTiming);
        cudaEventCreateWithFlags(&evJoin, cudaEventDisableTiming);
    }

    // Stream A: hist (also zeroes lookback state) -> lookback scan.
    hist_k<<<(E4 + tb - 1) / tb, tb>>>((const int4*)colp, E4, colp, E);
    scanlb_k<<<nb, 1024>>>(n, E);

    // Fork: prescale (needs only dinv from scanlb) overlaps scatter.
    cudaEventRecord(evFork, 0);
    cudaStreamWaitEvent(sB, evFork, 0);
    prescale_k<<<(n * F4 + tb - 1) / tb, tb, 0, sB>>>(x4, n);
    cudaEventRecord(evJoin, sB);

    scatter_k<<<(E4 + tb - 1) / tb, tb>>>((const int4*)rowp, (const int4*)colp,
                                          rowp, colp, E4, E);
    cudaStreamWaitEvent(0, evJoin, 0);        // join before step 1

    void *px, *pa, *pb, *ha, *hb;
    cudaGetSymbolAddress(&px, g_px);
    cudaGetSymbolAddress(&pa, g_pa);
    cudaGetSymbolAddress(&pb, g_pb);
    cudaGetSymbolAddress(&ha, g_h16a);
    cudaGetSymbolAddress(&hb, g_h16b);

    float4* f32buf[2] = {(float4*)pb, (float4*)pa};   // step i -> f32buf[i&1]
    uint2*  h16buf[2] = {(uint2*)ha, (uint2*)hb};     // P_i (fp16) -> h16buf[i&1]

    int grid = (n + NWARPS - 1) / NWARPS;

    for (int step = 1; step <= K; step++) {
        const uint2* h16 = h16buf[(step - 1) & 1];     // P_{i-1}
        uint2* p16out    = h16buf[step & 1];
        float4* pout     = f32buf[step & 1];
        const float4* pprev2 =
            (step <= 2) ? (const float4*)px                 // X' (P0) for steps 1,2
                        : (const float4*)f32buf[step & 1];  // same-parity buffer (RMW)
        spmm_k<<<grid, NWARPS * 32>>>(h16, pprev2, pout, p16out, out, x4,
                                      mf, lap, step, K, n);
    }
}